// round 12
// baseline (speedup 1.0000x reference)
#include <cuda_runtime.h>
#include <cuda_fp16.h>
#include <cstdint>

#define B_ 2
#define S_ 2048
#define D_ 1024
#define H_ 16
#define HD_ 64
#define MAXD 1024

typedef __half hf16;

// ---------------- scratch (__device__ globals; no allocs allowed) -----------
__device__ hf16 g_xh[B_*S_*D_], g_xl[B_*S_*D_];
__device__ hf16 g_qh[B_*S_*D_];
__device__ hf16 g_kh[B_*S_*D_], g_kl[B_*S_*D_];
__device__ hf16 g_vh[B_*S_*D_];
__device__ hf16 g_ah[B_*S_*D_];
__device__ hf16 g_wqh[D_*D_], g_wql[D_*D_];
__device__ hf16 g_wkh[D_*D_], g_wkl[D_*D_];
__device__ hf16 g_wvh[D_*D_], g_wvl[D_*D_];
__device__ hf16 g_woh[D_*D_], g_wol[D_*D_];

// ---------------- PTX helpers (arch-generic sm_80-era only) -----------------
__device__ __forceinline__ uint32_t s2u(const void* p) {
    uint32_t a;
    asm("{ .reg .u64 t; cvta.to.shared.u64 t, %1; cvt.u32.u64 %0, t; }" : "=r"(a) : "l"(p));
    return a;
}
#define CPA16(d, s) asm volatile("cp.async.cg.shared.global [%0], [%1], 16;" :: "r"(d), "l"(s))
#define CPC()       asm volatile("cp.async.commit_group;" ::: "memory")
#define CPW(n)      asm volatile("cp.async.wait_group %0;" :: "n"(n) : "memory")

__device__ __forceinline__ void ldm_x4(uint32_t* r, uint32_t addr) {
    asm volatile("ldmatrix.sync.aligned.m8n8.x4.shared.b16 {%0,%1,%2,%3}, [%4];"
                 : "=r"(r[0]), "=r"(r[1]), "=r"(r[2]), "=r"(r[3]) : "r"(addr));
}
__device__ __forceinline__ void ldm_x4_t(uint32_t* r, uint32_t addr) {
    asm volatile("ldmatrix.sync.aligned.m8n8.x4.trans.shared.b16 {%0,%1,%2,%3}, [%4];"
                 : "=r"(r[0]), "=r"(r[1]), "=r"(r[2]), "=r"(r[3]) : "r"(addr));
}
__device__ __forceinline__ void mma_f16(float* d, const uint32_t* a, const uint32_t* b) {
    asm volatile("mma.sync.aligned.m16n8k16.row.col.f32.f16.f16.f32 "
                 "{%0,%1,%2,%3}, {%4,%5,%6,%7}, {%8,%9}, {%0,%1,%2,%3};"
                 : "+f"(d[0]), "+f"(d[1]), "+f"(d[2]), "+f"(d[3])
                 : "r"(a[0]), "r"(a[1]), "r"(a[2]), "r"(a[3]), "r"(b[0]), "r"(b[1]));
}
__device__ __forceinline__ void split2h(float v0, float v1, uint32_t& hi, uint32_t& lo) {
    __half2 hb = __float22half2_rn(make_float2(v0, v1));
    float2 hfv = __half22float2(hb);
    __half2 lb = __float22half2_rn(make_float2(v0 - hfv.x, v1 - hfv.y));
    hi = *(uint32_t*)&hb;
    lo = *(uint32_t*)&lb;
}
__device__ __forceinline__ uint32_t pack2h(float v0, float v1) {
    __half2 p = __float22half2_rn(make_float2(v0, v1));
    return *(uint32_t*)&p;
}

// ---------------- fp32 -> (hi,lo) fp16 split --------------------------------
__global__ void cvt_split(const float* __restrict__ x, hf16* __restrict__ h,
                          hf16* __restrict__ l, int n4)
{
    int i = blockIdx.x * blockDim.x + threadIdx.x;
    if (i >= n4) return;
    float4 v = ((const float4*)x)[i];
    float vs[4] = {v.x, v.y, v.z, v.w};
    #pragma unroll
    for (int j = 0; j < 4; j++) {
        hf16 hb = __float2half_rn(vs[j]);
        h[i*4+j] = hb;
        l[i*4+j] = __float2half_rn(vs[j] - __half2float(hb));
    }
}

// ---------------- batched W[K,N] -> Wt[N,K] hi/lo split (z picks matrix) ----
__global__ void transpose_split4(const float* __restrict__ W0, const float* __restrict__ W1,
                                 const float* __restrict__ W2, const float* __restrict__ W3)
{
    __shared__ float t[32][33];
    int z = blockIdx.z;
    const float* W = z == 0 ? W0 : z == 1 ? W1 : z == 2 ? W2 : W3;
    hf16* Th = z == 0 ? g_wqh : z == 1 ? g_wkh : z == 2 ? g_wvh : g_woh;
    hf16* Tl = z == 0 ? g_wql : z == 1 ? g_wkl : z == 2 ? g_wvl : g_wol;

    int bx = blockIdx.x * 32, by = blockIdx.y * 32;
    int tx = threadIdx.x, ty = threadIdx.y;
    #pragma unroll
    for (int i = 0; i < 4; i++)
        t[ty + i*8][tx] = W[(size_t)(by + ty + i*8) * D_ + bx + tx];
    __syncthreads();
    #pragma unroll
    for (int i = 0; i < 4; i++) {
        float vv = t[tx][ty + i*8];
        hf16 hb = __float2half_rn(vv);
        size_t o = (size_t)(bx + ty + i*8) * D_ + by + tx;
        Th[o] = hb;
        Tl[o] = __float2half_rn(vv - __half2float(hb));
    }
}

// ---------------- shared GEMM body: C = A @ B^T (+bias), split-fp16 ---------
// P3: include the 3rd (Al*Bh) pass; when false, Al is never loaded at all.
#define NCHUNK 16
#define STAGE_BYTES 65536
template<bool OUT_F32, bool P3>
__device__ __forceinline__ void gemm_body(
    const hf16* __restrict__ Ah, const hf16* __restrict__ Al,
    const hf16* __restrict__ Bh, const hf16* __restrict__ Bl,
    const float* __restrict__ bias, float* __restrict__ Cf,
    hf16* __restrict__ Ch, hf16* __restrict__ Cl, char* smem)
{
    uint32_t sb = s2u(smem);
    int tid = threadIdx.x, wid = tid >> 5, lane = tid & 31;
    int wr = wid >> 2, wc = wid & 3;
    int rowBase = blockIdx.y * 128, colBase = blockIdx.x * 128;

    const hf16* bases[4] = {
        Ah + (size_t)rowBase * D_, P3 ? Al + (size_t)rowBase * D_ : nullptr,
        Bh + (size_t)colBase * D_, Bl + (size_t)colBase * D_ };

    #define LOAD_CHUNK(c_, st_) do { \
        int k0_ = (c_) * 64; \
        uint32_t d0_ = sb + (st_) * STAGE_BYTES; \
        _Pragma("unroll") \
        for (int t_ = 0; t_ < 4; t_++) { \
            if (!P3 && t_ == 1) continue; \
            const hf16* s_ = bases[t_]; \
            _Pragma("unroll") \
            for (int i_ = 0; i_ < 4; i_++) { \
                int idx_ = tid + i_ * 256; \
                int rr_ = idx_ >> 3, gq_ = idx_ & 7; \
                uint32_t dd_ = d0_ + t_ * 16384 + rr_ * 128 + ((gq_ ^ (rr_ & 7)) << 4); \
                CPA16(dd_, s_ + (size_t)rr_ * D_ + k0_ + gq_ * 8); \
            } \
        } \
        CPC(); \
    } while (0)

    LOAD_CHUNK(0, 0);
    LOAD_CHUNK(1, 1);

    float acc[4][4][4] = {};

    for (int c = 0; c < NCHUNK; c++) {
        if (c < NCHUNK - 1) CPW(1); else CPW(0);
        __syncthreads();
        if (c + 2 < NCHUNK) LOAD_CHUNK(c + 2, (c + 2) % 3);

        uint32_t stg = sb + (c % 3) * STAGE_BYTES;

        #pragma unroll
        for (int ks = 0; ks < 4; ks++) {
            uint32_t a_hi[4][4], a_lo[4][4];
            #pragma unroll
            for (int mi = 0; mi < 4; mi++) {
                int row = wr * 64 + mi * 16 + (lane & 15);
                int kg  = ks * 2 + (lane >> 4);
                uint32_t addr = stg + row * 128 + ((kg ^ (row & 7)) << 4);
                ldm_x4(a_hi[mi], addr);
                if (P3) ldm_x4(a_lo[mi], addr + 16384);
            }
            uint32_t b_hi[2][4], b_lo[2][4];
            #pragma unroll
            for (int nj = 0; nj < 2; nj++) {
                int rowb = wc * 32 + nj * 16 + (lane & 7) + ((lane & 16) ? 8 : 0);
                int kg   = ks * 2 + ((lane >> 3) & 1);
                uint32_t addr = stg + 32768 + rowb * 128 + ((kg ^ (rowb & 7)) << 4);
                ldm_x4(b_hi[nj], addr);
                ldm_x4(b_lo[nj], addr + 16384);
            }
            #pragma unroll
            for (int mi = 0; mi < 4; mi++)
                #pragma unroll
                for (int ni = 0; ni < 4; ni++) {
                    const uint32_t* bh = &b_hi[ni >> 1][(ni & 1) * 2];
                    const uint32_t* bl = &b_lo[ni >> 1][(ni & 1) * 2];
                    mma_f16(acc[mi][ni], a_hi[mi], bh);
                    mma_f16(acc[mi][ni], a_hi[mi], bl);
                    if (P3) mma_f16(acc[mi][ni], a_lo[mi], bh);
                }
        }
    }

    #pragma unroll
    for (int ni = 0; ni < 4; ni++) {
        int col = colBase + wc * 32 + ni * 8 + (lane & 3) * 2;
        float2 bb = bias ? *(const float2*)&bias[col] : make_float2(0.f, 0.f);
        #pragma unroll
        for (int mi = 0; mi < 4; mi++) {
            int row = rowBase + wr * 64 + mi * 16 + (lane >> 2);
            float v00 = acc[mi][ni][0] + bb.x, v01 = acc[mi][ni][1] + bb.y;
            float v10 = acc[mi][ni][2] + bb.x, v11 = acc[mi][ni][3] + bb.y;
            if (OUT_F32) {
                *(float2*)&Cf[(size_t)row * D_ + col]       = make_float2(v00, v01);
                *(float2*)&Cf[(size_t)(row + 8) * D_ + col] = make_float2(v10, v11);
            } else if (Cl) {
                uint32_t h0, l0, h1, l1;
                split2h(v00, v01, h0, l0);
                split2h(v10, v11, h1, l1);
                *(uint32_t*)&Ch[(size_t)row * D_ + col]       = h0;
                *(uint32_t*)&Cl[(size_t)row * D_ + col]       = l0;
                *(uint32_t*)&Ch[(size_t)(row + 8) * D_ + col] = h1;
                *(uint32_t*)&Cl[(size_t)(row + 8) * D_ + col] = l1;
            } else {
                *(uint32_t*)&Ch[(size_t)row * D_ + col]       = pack2h(v00, v01);
                *(uint32_t*)&Ch[(size_t)(row + 8) * D_ + col] = pack2h(v10, v11);
            }
        }
    }
}

// fused Q/K/V projection: blockIdx.z selects weight/bias/output.
// Q: 2-pass hi-only (flash uses qh only -> 3rd pass refines below fp16 rounding).
// K: 3-pass hi+lo (lo feeds the 2-pass QK^T). V: 2-pass hi-only.
__global__ void __launch_bounds__(256, 1)
gemm_qkv(const float* __restrict__ bq, const float* __restrict__ bv)
{
    extern __shared__ char smem[];
    int z = blockIdx.z;
    if (z == 1) {
        gemm_body<false, true >(g_xh, g_xl, g_wkh, g_wkl, nullptr, nullptr, g_kh, g_kl, smem);
    } else if (z == 0) {
        gemm_body<false, false>(g_xh, g_xl, g_wqh, g_wql, bq, nullptr, g_qh, nullptr, smem);
    } else {
        gemm_body<false, false>(g_xh, g_xl, g_wvh, g_wvl, bv, nullptr, g_vh, nullptr, smem);
    }
}

// output projection: fp32 out, 2-pass (attn output already fp16-rounded)
__global__ void __launch_bounds__(256, 1)
gemm_o(const float* __restrict__ bo, float* __restrict__ out)
{
    extern __shared__ char smem[];
    gemm_body<true, false>(g_ah, g_ah, g_woh, g_wol, bo, out, nullptr, nullptr, smem);
}

// ---------------------------------------------------------------------------
// Tensor-core flash attention, fp16. CTA = 128 q-rows x one (b,h), 128
// threads (4 warps x m32n64 -> 2 m16 sub-tiles each). 64-key chunks; stage =
// KH|KL|VH (24KB); ~90KB smem -> 2 CTAs/SM. Output: hi only (gemm_o 2-pass).
// ---------------------------------------------------------------------------
#define FA_Q    16384              // Q hi: 128 rows x 128B
#define FA_STAGE_SZ 24576          // KH 8KB | KL 8KB | VH 8KB
#define FA_TB   (FA_Q + 3*FA_STAGE_SZ)
#define FA_SMEM (FA_TB + 2*192*4)
#define NKT     (S_/64)

__global__ void __launch_bounds__(128)
flash_mma(const hf16* __restrict__ qh,
          const hf16* __restrict__ kh, const hf16* __restrict__ kl,
          const hf16* __restrict__ vh,
          const float* __restrict__ pb,
          hf16* __restrict__ oh)
{
    extern __shared__ char smem[];
    uint32_t sbase = s2u(smem);
    float* tb = (float*)(smem + FA_TB);

    int tid = threadIdx.x, w = tid >> 5, lane = tid & 31;
    int bh = blockIdx.y, b = bh >> 4, h = bh & 15;
    int q0 = blockIdx.x * 128;

    const float LOG2E = 1.4426950408889634f;
    const float c1L = 0.4785533905932738f * LOG2E;
    const float c2L = 0.3535533905932738f * LOG2E;

    size_t toff = (size_t)(b * S_) * D_ + h * HD_;
    const hf16* kvp[3] = {kh + toff, kl + toff, vh + toff};
    const hf16* qp = qh + toff;

    // ---- Q tile (128 rows x 64d, hi only), 16 KB ----
    #pragma unroll
    for (int i = 0; i < 8; i++) {
        int idx = tid + i * 128;           // 1024 granules
        int r = idx >> 3, g = idx & 7;
        uint32_t dd = sbase + r * 128 + ((g ^ (r & 7)) << 4);
        CPA16(dd, qp + (size_t)(q0 + r) * D_ + g * 8);
    }
    // 64-key chunk: KH | KL | VH at 8KB each
    #define LOAD_KV(c_, st_) do { \
        int kt_ = (c_) * 64; \
        uint32_t d0_ = sbase + FA_Q + (st_) * FA_STAGE_SZ; \
        _Pragma("unroll") \
        for (int t_ = 0; t_ < 3; t_++) { \
            _Pragma("unroll") \
            for (int i_ = 0; i_ < 4; i_++) { \
                int idx_ = tid + i_ * 128; \
                int r_ = idx_ >> 3, g_ = idx_ & 7; \
                uint32_t dd_ = d0_ + t_ * 8192 + r_ * 128 + ((g_ ^ (r_ & 7)) << 4); \
                CPA16(dd_, kvp[t_] + (size_t)(kt_ + r_) * D_ + g_ * 8); \
            } \
        } \
        CPC(); \
    } while (0)

    // bias table fill: 191 entries (i-j in [-63,127]), 128 threads -> strided
    #define FILL_TB(c_, buf_) do { \
        for (int t_ = tid; t_ < 191; t_ += 128) { \
            int rel_ = q0 - (c_) * 64 + (t_ - 63); \
            rel_ = min(max(rel_, -(MAXD - 1)), MAXD - 1) + (MAXD - 1); \
            tb[(buf_) * 192 + t_] = c2L * __ldg(&pb[rel_ * H_ + h]); \
        } \
    } while (0)

    LOAD_KV(0, 0);
    LOAD_KV(1, 1);
    FILL_TB(0, 0);

    uint32_t qa_h[2][4][4];
    float o[2][8][4] = {};
    float mr[2][2] = {{-1e30f, -1e30f}, {-1e30f, -1e30f}};
    float lr[2][2] = {};

    for (int c = 0; c < NKT; c++) {
        if (c < NKT - 1) CPW(1); else CPW(0);
        __syncthreads();

        if (c == 0) {
            #pragma unroll
            for (int mi = 0; mi < 2; mi++)
                #pragma unroll
                for (int ks = 0; ks < 4; ks++) {
                    int row = w * 32 + mi * 16 + (lane & 15);
                    int kg  = ks * 2 + (lane >> 4);
                    uint32_t addr = sbase + row * 128 + ((kg ^ (row & 7)) << 4);
                    ldm_x4(qa_h[mi][ks], addr);
                }
        }
        if (c + 2 < NKT) LOAD_KV(c + 2, (c + 2) % 3);
        if (c + 1 < NKT) FILL_TB(c + 1, (c + 1) & 1);

        uint32_t stg = sbase + FA_Q + (c % 3) * FA_STAGE_SZ;
        const float* tbc = tb + (c & 1) * 192;

        // ---- S = Qh (Kh + Kl): K fragments shared across both m16 tiles ----
        float s[2][8][4] = {};
        #pragma unroll
        for (int ks = 0; ks < 4; ks++) {
            uint32_t bK_h[4][4], bK_l[4][4];
            #pragma unroll
            for (int nj = 0; nj < 4; nj++) {
                int rowb = nj * 16 + (lane & 7) + ((lane & 16) ? 8 : 0);
                int kg   = ks * 2 + ((lane >> 3) & 1);
                uint32_t addr = stg + rowb * 128 + ((kg ^ (rowb & 7)) << 4);
                ldm_x4(bK_h[nj], addr);
                ldm_x4(bK_l[nj], addr + 8192);
            }
            #pragma unroll
            for (int mi = 0; mi < 2; mi++)
                #pragma unroll
                for (int ni = 0; ni < 8; ni++) {
                    const uint32_t* bh2 = &bK_h[ni >> 1][(ni & 1) * 2];
                    const uint32_t* bl2 = &bK_l[ni >> 1][(ni & 1) * 2];
                    mma_f16(s[mi][ni], qa_h[mi][ks], bh2);
                    mma_f16(s[mi][ni], qa_h[mi][ks], bl2);
                }
        }

        // ---- bias + online softmax (exp2 domain), per m16 sub-tile ----
        int jb = 2 * (lane & 3);
        #pragma unroll
        for (int mi = 0; mi < 2; mi++) {
            int i0 = w * 32 + mi * 16 + (lane >> 2);
            float t0 = -1e30f, t1 = -1e30f;
            #pragma unroll
            for (int ni = 0; ni < 8; ni++) {
                int tix = i0 - (8 * ni + jb) + 63;
                s[mi][ni][0] = fmaf(c1L, s[mi][ni][0], tbc[tix]);
                s[mi][ni][1] = fmaf(c1L, s[mi][ni][1], tbc[tix - 1]);
                s[mi][ni][2] = fmaf(c1L, s[mi][ni][2], tbc[tix + 8]);
                s[mi][ni][3] = fmaf(c1L, s[mi][ni][3], tbc[tix + 7]);
                t0 = fmaxf(t0, fmaxf(s[mi][ni][0], s[mi][ni][1]));
                t1 = fmaxf(t1, fmaxf(s[mi][ni][2], s[mi][ni][3]));
            }
            t0 = fmaxf(t0, __shfl_xor_sync(0xffffffffu, t0, 1));
            t0 = fmaxf(t0, __shfl_xor_sync(0xffffffffu, t0, 2));
            t1 = fmaxf(t1, __shfl_xor_sync(0xffffffffu, t1, 1));
            t1 = fmaxf(t1, __shfl_xor_sync(0xffffffffu, t1, 2));
            float m0n = fmaxf(mr[mi][0], t0), m1n = fmaxf(mr[mi][1], t1);
            float cr0 = exp2f(mr[mi][0] - m0n), cr1 = exp2f(mr[mi][1] - m1n);
            mr[mi][0] = m0n; mr[mi][1] = m1n;

            float ls0 = 0.f, ls1 = 0.f;
            #pragma unroll
            for (int ni = 0; ni < 8; ni++) {
                s[mi][ni][0] = exp2f(s[mi][ni][0] - m0n);
                s[mi][ni][1] = exp2f(s[mi][ni][1] - m0n);
                s[mi][ni][2] = exp2f(s[mi][ni][2] - m1n);
                s[mi][ni][3] = exp2f(s[mi][ni][3] - m1n);
                ls0 += s[mi][ni][0] + s[mi][ni][1];
                ls1 += s[mi][ni][2] + s[mi][ni][3];
            }
            lr[mi][0] = lr[mi][0] * cr0 + ls0;
            lr[mi][1] = lr[mi][1] * cr1 + ls1;
            if (cr0 != 1.f || cr1 != 1.f) {
                #pragma unroll
                for (int ni = 0; ni < 8; ni++) {
                    o[mi][ni][0] *= cr0; o[mi][ni][1] *= cr0;
                    o[mi][ni][2] *= cr1; o[mi][ni][3] *= cr1;
                }
            }
        }

        // ---- O += P V: V fragments shared across both m16 tiles ----
        #pragma unroll
        for (int t = 0; t < 4; t++) {
            uint32_t bV_h[4][4];
            #pragma unroll
            for (int vj = 0; vj < 4; vj++) {
                int rowv = t * 16 + (lane & 7) + ((lane & 8) ? 8 : 0);
                int gq   = 2 * vj + ((lane >> 4) & 1);
                uint32_t addr = stg + 16384 + rowv * 128 + ((gq ^ (rowv & 7)) << 4);
                ldm_x4_t(bV_h[vj], addr);
            }
            #pragma unroll
            for (int mi = 0; mi < 2; mi++) {
                uint32_t a_h[4];
                a_h[0] = pack2h(s[mi][2*t][0],   s[mi][2*t][1]);
                a_h[1] = pack2h(s[mi][2*t][2],   s[mi][2*t][3]);
                a_h[2] = pack2h(s[mi][2*t+1][0], s[mi][2*t+1][1]);
                a_h[3] = pack2h(s[mi][2*t+1][2], s[mi][2*t+1][3]);
                #pragma unroll
                for (int ni = 0; ni < 8; ni++) {
                    const uint32_t* bh2 = &bV_h[ni >> 1][(ni & 1) * 2];
                    mma_f16(o[mi][ni], a_h, bh2);
                }
            }
        }
    }

    #pragma unroll
    for (int mi = 0; mi < 2; mi++) {
        float l0 = lr[mi][0], l1 = lr[mi][1];
        l0 += __shfl_xor_sync(0xffffffffu, l0, 1);
        l0 += __shfl_xor_sync(0xffffffffu, l0, 2);
        l1 += __shfl_xor_sync(0xffffffffu, l1, 1);
        l1 += __shfl_xor_sync(0xffffffffu, l1, 2);
        float inv0 = 1.f / l0, inv1 = 1.f / l1;

        int row0 = b * S_ + q0 + w * 32 + mi * 16 + (lane >> 2);
        #pragma unroll
        for (int ni = 0; ni < 8; ni++) {
            int col = h * HD_ + 8 * ni + 2 * (lane & 3);
            *(uint32_t*)&oh[(size_t)row0 * D_ + col]       = pack2h(o[mi][ni][0] * inv0, o[mi][ni][1] * inv0);
            *(uint32_t*)&oh[(size_t)(row0 + 8) * D_ + col] = pack2h(o[mi][ni][2] * inv1, o[mi][ni][3] * inv1);
        }
    }
}

// ---------------------------------------------------------------------------
extern "C" void kernel_launch(void* const* d_in, const int* in_sizes, int n_in,
                              void* d_out, int out_size)
{
    const float* x  = (const float*)d_in[0];
    const float* Wq = (const float*)d_in[1];
    const float* bq = (const float*)d_in[2];
    const float* Wk = (const float*)d_in[3];
    const float* Wv = (const float*)d_in[4];
    const float* bv = (const float*)d_in[5];
    const float* Wo = (const float*)d_in[6];
    const float* bo = (const float*)d_in[7];
    const float* pb = (const float*)d_in[8];
    float* out = (float*)d_out;

    hf16 *xh, *xl, *qh, *kh, *kl, *vh, *ah;
    cudaGetSymbolAddress((void**)&xh, g_xh); cudaGetSymbolAddress((void**)&xl, g_xl);
    cudaGetSymbolAddress((void**)&qh, g_qh);
    cudaGetSymbolAddress((void**)&kh, g_kh); cudaGetSymbolAddress((void**)&kl, g_kl);
    cudaGetSymbolAddress((void**)&vh, g_vh);
    cudaGetSymbolAddress((void**)&ah, g_ah);

    const int M = B_ * S_;
    const int NELEM4 = M * D_ / 4;

    cvt_split<<<NELEM4 / 256, 256>>>(x, xh, xl, NELEM4);
    dim3 tGrid(D_ / 32, D_ / 32, 4), tBlk(32, 8);
    transpose_split4<<<tGrid, tBlk>>>(Wq, Wk, Wv, Wo);

    int gsmem = 3 * STAGE_BYTES;
    cudaFuncSetAttribute(gemm_qkv, cudaFuncAttributeMaxDynamicSharedMemorySize, gsmem);
    cudaFuncSetAttribute(gemm_o,   cudaFuncAttributeMaxDynamicSharedMemorySize, gsmem);

    dim3 qkvGrid(D_ / 128, M / 128, 3);          // (8, 32, 3)
    gemm_qkv<<<qkvGrid, 256, gsmem>>>(bq, bv);

    cudaFuncSetAttribute(flash_mma, cudaFuncAttributeMaxDynamicSharedMemorySize, FA_SMEM);
    dim3 fGrid(S_ / 128, B_ * H_);               // (16, 32)
    flash_mma<<<fGrid, 128, FA_SMEM>>>(qh, kh, kl, vh, pb, ah);

    dim3 oGrid(D_ / 128, M / 128);               // (8, 32)
    gemm_o<<<oGrid, 256, gsmem>>>(bo, out);
}

// round 13
// speedup vs baseline: 1.4040x; 1.4040x over previous
#include <cuda_runtime.h>
#include <cuda_fp16.h>
#include <cstdint>

#define B_ 2
#define S_ 2048
#define D_ 1024
#define H_ 16
#define HD_ 64
#define MAXD 1024

typedef __half hf16;

// ---------------- scratch (__device__ globals; no allocs allowed) -----------
__device__ hf16 g_xh[B_*S_*D_], g_xl[B_*S_*D_];
__device__ hf16 g_qh[B_*S_*D_];
__device__ hf16 g_kh[B_*S_*D_], g_kl[B_*S_*D_];
__device__ hf16 g_vh[B_*S_*D_];
__device__ hf16 g_ah[B_*S_*D_];
__device__ hf16 g_wqh[D_*D_], g_wql[D_*D_];
__device__ hf16 g_wkh[D_*D_], g_wkl[D_*D_];
__device__ hf16 g_wvh[D_*D_], g_wvl[D_*D_];
__device__ hf16 g_woh[D_*D_], g_wol[D_*D_];

// ---------------- PTX helpers (arch-generic sm_80-era only) -----------------
__device__ __forceinline__ uint32_t s2u(const void* p) {
    uint32_t a;
    asm("{ .reg .u64 t; cvta.to.shared.u64 t, %1; cvt.u32.u64 %0, t; }" : "=r"(a) : "l"(p));
    return a;
}
#define CPA16(d, s) asm volatile("cp.async.cg.shared.global [%0], [%1], 16;" :: "r"(d), "l"(s))
#define CPC()       asm volatile("cp.async.commit_group;" ::: "memory")
#define CPW(n)      asm volatile("cp.async.wait_group %0;" :: "n"(n) : "memory")

__device__ __forceinline__ void ldm_x4(uint32_t* r, uint32_t addr) {
    asm volatile("ldmatrix.sync.aligned.m8n8.x4.shared.b16 {%0,%1,%2,%3}, [%4];"
                 : "=r"(r[0]), "=r"(r[1]), "=r"(r[2]), "=r"(r[3]) : "r"(addr));
}
__device__ __forceinline__ void ldm_x4_t(uint32_t* r, uint32_t addr) {
    asm volatile("ldmatrix.sync.aligned.m8n8.x4.trans.shared.b16 {%0,%1,%2,%3}, [%4];"
                 : "=r"(r[0]), "=r"(r[1]), "=r"(r[2]), "=r"(r[3]) : "r"(addr));
}
__device__ __forceinline__ void mma_f16(float* d, const uint32_t* a, const uint32_t* b) {
    asm volatile("mma.sync.aligned.m16n8k16.row.col.f32.f16.f16.f32 "
                 "{%0,%1,%2,%3}, {%4,%5,%6,%7}, {%8,%9}, {%0,%1,%2,%3};"
                 : "+f"(d[0]), "+f"(d[1]), "+f"(d[2]), "+f"(d[3])
                 : "r"(a[0]), "r"(a[1]), "r"(a[2]), "r"(a[3]), "r"(b[0]), "r"(b[1]));
}
__device__ __forceinline__ void split2h(float v0, float v1, uint32_t& hi, uint32_t& lo) {
    __half2 hb = __float22half2_rn(make_float2(v0, v1));
    float2 hfv = __half22float2(hb);
    __half2 lb = __float22half2_rn(make_float2(v0 - hfv.x, v1 - hfv.y));
    hi = *(uint32_t*)&hb;
    lo = *(uint32_t*)&lb;
}
__device__ __forceinline__ uint32_t pack2h(float v0, float v1) {
    __half2 p = __float22half2_rn(make_float2(v0, v1));
    return *(uint32_t*)&p;
}

// ---------------- fp32 -> (hi,lo) fp16 split --------------------------------
__global__ void cvt_split(const float* __restrict__ x, hf16* __restrict__ h,
                          hf16* __restrict__ l, int n4)
{
    int i = blockIdx.x * blockDim.x + threadIdx.x;
    if (i >= n4) return;
    float4 v = ((const float4*)x)[i];
    float vs[4] = {v.x, v.y, v.z, v.w};
    #pragma unroll
    for (int j = 0; j < 4; j++) {
        hf16 hb = __float2half_rn(vs[j]);
        h[i*4+j] = hb;
        l[i*4+j] = __float2half_rn(vs[j] - __half2float(hb));
    }
}

// ---------------- batched W[K,N] -> Wt[N,K] hi/lo split (z picks matrix) ----
__global__ void transpose_split4(const float* __restrict__ W0, const float* __restrict__ W1,
                                 const float* __restrict__ W2, const float* __restrict__ W3)
{
    __shared__ float t[32][33];
    int z = blockIdx.z;
    const float* W = z == 0 ? W0 : z == 1 ? W1 : z == 2 ? W2 : W3;
    hf16* Th = z == 0 ? g_wqh : z == 1 ? g_wkh : z == 2 ? g_wvh : g_woh;
    hf16* Tl = z == 0 ? g_wql : z == 1 ? g_wkl : z == 2 ? g_wvl : g_wol;

    int bx = blockIdx.x * 32, by = blockIdx.y * 32;
    int tx = threadIdx.x, ty = threadIdx.y;
    #pragma unroll
    for (int i = 0; i < 4; i++)
        t[ty + i*8][tx] = W[(size_t)(by + ty + i*8) * D_ + bx + tx];
    __syncthreads();
    #pragma unroll
    for (int i = 0; i < 4; i++) {
        float vv = t[tx][ty + i*8];
        hf16 hb = __float2half_rn(vv);
        size_t o = (size_t)(bx + ty + i*8) * D_ + by + tx;
        Th[o] = hb;
        Tl[o] = __float2half_rn(vv - __half2float(hb));
    }
}

// ---------------- shared GEMM body: C = A @ B^T (+bias), split-fp16 ---------
// p3 (runtime): include the 3rd (Al*Bh) pass; when false, A_lo tile is not
// even loaded. Single instantiation per OUT_F32 to keep code size in I$.
#define NCHUNK 16
#define STAGE_BYTES 65536
template<bool OUT_F32>
__device__ __forceinline__ void gemm_body(
    const hf16* __restrict__ Ah, const hf16* __restrict__ Al,
    const hf16* __restrict__ Bh, const hf16* __restrict__ Bl,
    const float* __restrict__ bias, float* __restrict__ Cf,
    hf16* __restrict__ Ch, hf16* __restrict__ Cl, char* smem, bool p3)
{
    uint32_t sb = s2u(smem);
    int tid = threadIdx.x, wid = tid >> 5, lane = tid & 31;
    int wr = wid >> 2, wc = wid & 3;
    int rowBase = blockIdx.y * 128, colBase = blockIdx.x * 128;

    const hf16* bases[4] = {
        Ah + (size_t)rowBase * D_, Al + (size_t)rowBase * D_,
        Bh + (size_t)colBase * D_, Bl + (size_t)colBase * D_ };

    #define LOAD_CHUNK(c_, st_) do { \
        int k0_ = (c_) * 64; \
        uint32_t d0_ = sb + (st_) * STAGE_BYTES; \
        _Pragma("unroll") \
        for (int t_ = 0; t_ < 4; t_++) { \
            if (t_ == 1 && !p3) continue; \
            const hf16* s_ = bases[t_]; \
            _Pragma("unroll") \
            for (int i_ = 0; i_ < 4; i_++) { \
                int idx_ = tid + i_ * 256; \
                int rr_ = idx_ >> 3, gq_ = idx_ & 7; \
                uint32_t dd_ = d0_ + t_ * 16384 + rr_ * 128 + ((gq_ ^ (rr_ & 7)) << 4); \
                CPA16(dd_, s_ + (size_t)rr_ * D_ + k0_ + gq_ * 8); \
            } \
        } \
        CPC(); \
    } while (0)

    LOAD_CHUNK(0, 0);
    LOAD_CHUNK(1, 1);

    float acc[4][4][4] = {};

    for (int c = 0; c < NCHUNK; c++) {
        if (c < NCHUNK - 1) CPW(1); else CPW(0);
        __syncthreads();
        if (c + 2 < NCHUNK) LOAD_CHUNK(c + 2, (c + 2) % 3);

        uint32_t stg = sb + (c % 3) * STAGE_BYTES;

        #pragma unroll
        for (int ks = 0; ks < 4; ks++) {
            uint32_t a_hi[4][4], a_lo[4][4];
            #pragma unroll
            for (int mi = 0; mi < 4; mi++) {
                int row = wr * 64 + mi * 16 + (lane & 15);
                int kg  = ks * 2 + (lane >> 4);
                uint32_t addr = stg + row * 128 + ((kg ^ (row & 7)) << 4);
                ldm_x4(a_hi[mi], addr);
                if (p3) ldm_x4(a_lo[mi], addr + 16384);
            }
            uint32_t b_hi[2][4], b_lo[2][4];
            #pragma unroll
            for (int nj = 0; nj < 2; nj++) {
                int rowb = wc * 32 + nj * 16 + (lane & 7) + ((lane & 16) ? 8 : 0);
                int kg   = ks * 2 + ((lane >> 3) & 1);
                uint32_t addr = stg + 32768 + rowb * 128 + ((kg ^ (rowb & 7)) << 4);
                ldm_x4(b_hi[nj], addr);
                ldm_x4(b_lo[nj], addr + 16384);
            }
            #pragma unroll
            for (int mi = 0; mi < 4; mi++)
                #pragma unroll
                for (int ni = 0; ni < 4; ni++) {
                    const uint32_t* bh = &b_hi[ni >> 1][(ni & 1) * 2];
                    const uint32_t* bl = &b_lo[ni >> 1][(ni & 1) * 2];
                    mma_f16(acc[mi][ni], a_hi[mi], bh);
                    mma_f16(acc[mi][ni], a_hi[mi], bl);
                    if (p3) mma_f16(acc[mi][ni], a_lo[mi], bh);
                }
        }
    }

    #pragma unroll
    for (int ni = 0; ni < 4; ni++) {
        int col = colBase + wc * 32 + ni * 8 + (lane & 3) * 2;
        float2 bb = bias ? *(const float2*)&bias[col] : make_float2(0.f, 0.f);
        #pragma unroll
        for (int mi = 0; mi < 4; mi++) {
            int row = rowBase + wr * 64 + mi * 16 + (lane >> 2);
            float v00 = acc[mi][ni][0] + bb.x, v01 = acc[mi][ni][1] + bb.y;
            float v10 = acc[mi][ni][2] + bb.x, v11 = acc[mi][ni][3] + bb.y;
            if (OUT_F32) {
                *(float2*)&Cf[(size_t)row * D_ + col]       = make_float2(v00, v01);
                *(float2*)&Cf[(size_t)(row + 8) * D_ + col] = make_float2(v10, v11);
            } else if (Cl) {
                uint32_t h0, l0, h1, l1;
                split2h(v00, v01, h0, l0);
                split2h(v10, v11, h1, l1);
                *(uint32_t*)&Ch[(size_t)row * D_ + col]       = h0;
                *(uint32_t*)&Cl[(size_t)row * D_ + col]       = l0;
                *(uint32_t*)&Ch[(size_t)(row + 8) * D_ + col] = h1;
                *(uint32_t*)&Cl[(size_t)(row + 8) * D_ + col] = l1;
            } else {
                *(uint32_t*)&Ch[(size_t)row * D_ + col]       = pack2h(v00, v01);
                *(uint32_t*)&Ch[(size_t)(row + 8) * D_ + col] = pack2h(v10, v11);
            }
        }
    }
}

// fused Q/K/V projection: blockIdx.z selects weight/bias/output.
// Q: 2-pass hi-only (flash uses qh only). K: 3-pass hi+lo (lo feeds QK^T).
// V: 2-pass hi-only.
__global__ void __launch_bounds__(256, 1)
gemm_qkv(const float* __restrict__ bq, const float* __restrict__ bv)
{
    extern __shared__ char smem[];
    int z = blockIdx.z;
    const hf16* Bh = z == 0 ? g_wqh : z == 1 ? g_wkh : g_wvh;
    const hf16* Bl = z == 0 ? g_wql : z == 1 ? g_wkl : g_wvl;
    const float* bias = z == 0 ? bq : z == 1 ? (const float*)nullptr : bv;
    hf16* Ch = z == 0 ? g_qh : z == 1 ? g_kh : g_vh;
    hf16* Cl = z == 1 ? g_kl : (hf16*)nullptr;
    gemm_body<false>(g_xh, g_xl, Bh, Bl, bias, nullptr, Ch, Cl, smem, z == 1);
}

// output projection: fp32 out, 2-pass (attn output already fp16-rounded)
__global__ void __launch_bounds__(256, 1)
gemm_o(const float* __restrict__ bo, float* __restrict__ out)
{
    extern __shared__ char smem[];
    gemm_body<true>(g_ah, g_ah, g_woh, g_wol, bo, out, nullptr, nullptr, smem, false);
}

// ---------------------------------------------------------------------------
// Tensor-core flash attention, fp16 (R9-proven m16 structure). CTA = 64
// q-rows x one (b,h), 128 threads (4 warps x m16n64). 64-key chunks; stage =
// KH|KL|VH (24KB); ~82KB smem -> 2 CTAs/SM. S = Qh(Kh+Kl); O = P V; output
// hi-only (gemm_o runs 2-pass).
// ---------------------------------------------------------------------------
#define FA_STG  8192               // Q hi = 8KB
#define FA_STAGE_SZ 24576          // KH 8KB | KL 8KB | VH 8KB
#define FA_TB   (FA_STG + 3*FA_STAGE_SZ)
#define FA_SMEM (FA_TB + 2*128*4)
#define NKT     (S_/64)

__global__ void __launch_bounds__(128)
flash_mma(const hf16* __restrict__ qh,
          const hf16* __restrict__ kh, const hf16* __restrict__ kl,
          const hf16* __restrict__ vh,
          const float* __restrict__ pb,
          hf16* __restrict__ oh)
{
    extern __shared__ char smem[];
    uint32_t sbase = s2u(smem);
    float* tb = (float*)(smem + FA_TB);

    int tid = threadIdx.x, w = tid >> 5, lane = tid & 31;
    int bh = blockIdx.y, b = bh >> 4, h = bh & 15;
    int q0 = blockIdx.x * 64;

    const float LOG2E = 1.4426950408889634f;
    const float c1L = 0.4785533905932738f * LOG2E;
    const float c2L = 0.3535533905932738f * LOG2E;

    size_t toff = (size_t)(b * S_) * D_ + h * HD_;
    const hf16* kvp[3] = {kh + toff, kl + toff, vh + toff};
    const hf16* qp = qh + toff;

    // ---- Q tile (64 rows x 64d, hi only), 8 KB ----
    #pragma unroll
    for (int i = 0; i < 4; i++) {
        int idx = tid + i * 128;           // 512 granules
        int r = idx >> 3, g = idx & 7;
        uint32_t dd = sbase + r * 128 + ((g ^ (r & 7)) << 4);
        CPA16(dd, qp + (size_t)(q0 + r) * D_ + g * 8);
    }
    // 64-key chunk: KH | KL | VH at 8KB each
    #define LOAD_KV(c_, st_) do { \
        int kt_ = (c_) * 64; \
        uint32_t d0_ = sbase + FA_STG + (st_) * FA_STAGE_SZ; \
        _Pragma("unroll") \
        for (int t_ = 0; t_ < 3; t_++) { \
            _Pragma("unroll") \
            for (int i_ = 0; i_ < 4; i_++) { \
                int idx_ = tid + i_ * 128; \
                int r_ = idx_ >> 3, g_ = idx_ & 7; \
                uint32_t dd_ = d0_ + t_ * 8192 + r_ * 128 + ((g_ ^ (r_ & 7)) << 4); \
                CPA16(dd_, kvp[t_] + (size_t)(kt_ + r_) * D_ + g_ * 8); \
            } \
        } \
        CPC(); \
    } while (0)

    LOAD_KV(0, 0);
    LOAD_KV(1, 1);

    if (tid < 127) {
        int rel = q0 - 0 + (tid - 63);
        rel = min(max(rel, -(MAXD - 1)), MAXD - 1) + (MAXD - 1);
        tb[tid] = c2L * __ldg(&pb[rel * H_ + h]);
    }

    uint32_t qa_h[4][4];
    float o[8][4] = {};
    float m0 = -1e30f, m1 = -1e30f, l0 = 0.f, l1 = 0.f;

    for (int c = 0; c < NKT; c++) {
        if (c < NKT - 1) CPW(1); else CPW(0);
        __syncthreads();

        if (c == 0) {
            #pragma unroll
            for (int ks = 0; ks < 4; ks++) {
                int row = w * 16 + (lane & 15);
                int kg  = ks * 2 + (lane >> 4);
                uint32_t addr = sbase + row * 128 + ((kg ^ (row & 7)) << 4);
                ldm_x4(qa_h[ks], addr);
            }
        }
        if (c + 2 < NKT) LOAD_KV(c + 2, (c + 2) % 3);
        if (c + 1 < NKT && tid < 127) {
            int rel = q0 - (c + 1) * 64 + (tid - 63);
            rel = min(max(rel, -(MAXD - 1)), MAXD - 1) + (MAXD - 1);
            tb[((c + 1) & 1) * 128 + tid] = c2L * __ldg(&pb[rel * H_ + h]);
        }

        uint32_t stg = sbase + FA_STG + (c % 3) * FA_STAGE_SZ;
        const float* tbc = tb + (c & 1) * 128;

        // ---- S = Qh (Kh + Kl)  (2-pass split-fp16) ----
        float s[8][4] = {};
        #pragma unroll
        for (int ks = 0; ks < 4; ks++) {
            uint32_t bK_h[4][4], bK_l[4][4];
            #pragma unroll
            for (int nj = 0; nj < 4; nj++) {
                int rowb = nj * 16 + (lane & 7) + ((lane & 16) ? 8 : 0);
                int kg   = ks * 2 + ((lane >> 3) & 1);
                uint32_t addr = stg + rowb * 128 + ((kg ^ (rowb & 7)) << 4);
                ldm_x4(bK_h[nj], addr);
                ldm_x4(bK_l[nj], addr + 8192);
            }
            #pragma unroll
            for (int ni = 0; ni < 8; ni++) {
                const uint32_t* bh2 = &bK_h[ni >> 1][(ni & 1) * 2];
                const uint32_t* bl2 = &bK_l[ni >> 1][(ni & 1) * 2];
                mma_f16(s[ni], qa_h[ks], bh2);
                mma_f16(s[ni], qa_h[ks], bl2);
            }
        }

        // ---- bias + online softmax (exp2 domain) ----
        int i0 = w * 16 + (lane >> 2);
        int jb = 2 * (lane & 3);
        float t0 = -1e30f, t1 = -1e30f;
        #pragma unroll
        for (int ni = 0; ni < 8; ni++) {
            int tix = i0 - (8 * ni + jb) + 63;
            s[ni][0] = fmaf(c1L, s[ni][0], tbc[tix]);
            s[ni][1] = fmaf(c1L, s[ni][1], tbc[tix - 1]);
            s[ni][2] = fmaf(c1L, s[ni][2], tbc[tix + 8]);
            s[ni][3] = fmaf(c1L, s[ni][3], tbc[tix + 7]);
            t0 = fmaxf(t0, fmaxf(s[ni][0], s[ni][1]));
            t1 = fmaxf(t1, fmaxf(s[ni][2], s[ni][3]));
        }
        t0 = fmaxf(t0, __shfl_xor_sync(0xffffffffu, t0, 1));
        t0 = fmaxf(t0, __shfl_xor_sync(0xffffffffu, t0, 2));
        t1 = fmaxf(t1, __shfl_xor_sync(0xffffffffu, t1, 1));
        t1 = fmaxf(t1, __shfl_xor_sync(0xffffffffu, t1, 2));
        float m0n = fmaxf(m0, t0), m1n = fmaxf(m1, t1);
        float cr0 = exp2f(m0 - m0n), cr1 = exp2f(m1 - m1n);
        m0 = m0n; m1 = m1n;

        float ls0 = 0.f, ls1 = 0.f;
        #pragma unroll
        for (int ni = 0; ni < 8; ni++) {
            s[ni][0] = exp2f(s[ni][0] - m0);
            s[ni][1] = exp2f(s[ni][1] - m0);
            s[ni][2] = exp2f(s[ni][2] - m1);
            s[ni][3] = exp2f(s[ni][3] - m1);
            ls0 += s[ni][0] + s[ni][1];
            ls1 += s[ni][2] + s[ni][3];
        }
        l0 = l0 * cr0 + ls0;
        l1 = l1 * cr1 + ls1;
        if (cr0 != 1.f || cr1 != 1.f) {
            #pragma unroll
            for (int ni = 0; ni < 8; ni++) {
                o[ni][0] *= cr0; o[ni][1] *= cr0;
                o[ni][2] *= cr1; o[ni][3] *= cr1;
            }
        }

        // ---- O += P V (single-pass fp16) ----
        #pragma unroll
        for (int t = 0; t < 4; t++) {
            uint32_t a_h[4];
            a_h[0] = pack2h(s[2*t][0],   s[2*t][1]);
            a_h[1] = pack2h(s[2*t][2],   s[2*t][3]);
            a_h[2] = pack2h(s[2*t+1][0], s[2*t+1][1]);
            a_h[3] = pack2h(s[2*t+1][2], s[2*t+1][3]);

            uint32_t bV_h[4][4];
            #pragma unroll
            for (int vj = 0; vj < 4; vj++) {
                int rowv = t * 16 + (lane & 7) + ((lane & 8) ? 8 : 0);
                int gq   = 2 * vj + ((lane >> 4) & 1);
                uint32_t addr = stg + 16384 + rowv * 128 + ((gq ^ (rowv & 7)) << 4);
                ldm_x4_t(bV_h[vj], addr);
            }
            #pragma unroll
            for (int ni = 0; ni < 8; ni++) {
                const uint32_t* bh2 = &bV_h[ni >> 1][(ni & 1) * 2];
                mma_f16(o[ni], a_h, bh2);
            }
        }
    }

    l0 += __shfl_xor_sync(0xffffffffu, l0, 1);
    l0 += __shfl_xor_sync(0xffffffffu, l0, 2);
    l1 += __shfl_xor_sync(0xffffffffu, l1, 1);
    l1 += __shfl_xor_sync(0xffffffffu, l1, 2);
    float inv0 = 1.f / l0, inv1 = 1.f / l1;

    int row0 = b * S_ + q0 + w * 16 + (lane >> 2);
    #pragma unroll
    for (int ni = 0; ni < 8; ni++) {
        int col = h * HD_ + 8 * ni + 2 * (lane & 3);
        *(uint32_t*)&oh[(size_t)row0 * D_ + col]       = pack2h(o[ni][0] * inv0, o[ni][1] * inv0);
        *(uint32_t*)&oh[(size_t)(row0 + 8) * D_ + col] = pack2h(o[ni][2] * inv1, o[ni][3] * inv1);
    }
}

// ---------------------------------------------------------------------------
extern "C" void kernel_launch(void* const* d_in, const int* in_sizes, int n_in,
                              void* d_out, int out_size)
{
    const float* x  = (const float*)d_in[0];
    const float* Wq = (const float*)d_in[1];
    const float* bq = (const float*)d_in[2];
    const float* Wk = (const float*)d_in[3];
    const float* Wv = (const float*)d_in[4];
    const float* bv = (const float*)d_in[5];
    const float* Wo = (const float*)d_in[6];
    const float* bo = (const float*)d_in[7];
    const float* pb = (const float*)d_in[8];
    float* out = (float*)d_out;

    hf16 *xh, *xl, *qh, *kh, *kl, *vh, *ah;
    cudaGetSymbolAddress((void**)&xh, g_xh); cudaGetSymbolAddress((void**)&xl, g_xl);
    cudaGetSymbolAddress((void**)&qh, g_qh);
    cudaGetSymbolAddress((void**)&kh, g_kh); cudaGetSymbolAddress((void**)&kl, g_kl);
    cudaGetSymbolAddress((void**)&vh, g_vh);
    cudaGetSymbolAddress((void**)&ah, g_ah);

    const int M = B_ * S_;
    const int NELEM4 = M * D_ / 4;

    cvt_split<<<NELEM4 / 256, 256>>>(x, xh, xl, NELEM4);
    dim3 tGrid(D_ / 32, D_ / 32, 4), tBlk(32, 8);
    transpose_split4<<<tGrid, tBlk>>>(Wq, Wk, Wv, Wo);

    int gsmem = 3 * STAGE_BYTES;
    cudaFuncSetAttribute(gemm_qkv, cudaFuncAttributeMaxDynamicSharedMemorySize, gsmem);
    cudaFuncSetAttribute(gemm_o,   cudaFuncAttributeMaxDynamicSharedMemorySize, gsmem);

    dim3 qkvGrid(D_ / 128, M / 128, 3);          // (8, 32, 3)
    gemm_qkv<<<qkvGrid, 256, gsmem>>>(bq, bv);

    cudaFuncSetAttribute(flash_mma, cudaFuncAttributeMaxDynamicSharedMemorySize, FA_SMEM);
    dim3 fGrid(S_ / 64, B_ * H_);                // (32, 32)
    flash_mma<<<fGrid, 128, FA_SMEM>>>(qh, kh, kl, vh, pb, ah);

    dim3 oGrid(D_ / 128, M / 128);               // (8, 32)
    gemm_o<<<oGrid, 256, gsmem>>>(bo, out);
}

// round 14
// speedup vs baseline: 1.4244x; 1.0145x over previous
#include <cuda_runtime.h>
#include <cuda_fp16.h>
#include <cstdint>

#define B_ 2
#define S_ 2048
#define D_ 1024
#define H_ 16
#define HD_ 64
#define MAXD 1024

typedef __half hf16;

// ---------------- scratch (__device__ globals; no allocs allowed) -----------
__device__ hf16 g_xh[B_*S_*D_], g_xl[B_*S_*D_];
__device__ hf16 g_qh[B_*S_*D_];
__device__ hf16 g_kh[B_*S_*D_], g_kl[B_*S_*D_];
__device__ hf16 g_vh[B_*S_*D_];
__device__ hf16 g_ah[B_*S_*D_];
__device__ hf16 g_wqh[D_*D_], g_wql[D_*D_];
__device__ hf16 g_wkh[D_*D_], g_wkl[D_*D_];
__device__ hf16 g_wvh[D_*D_], g_wvl[D_*D_];
__device__ hf16 g_woh[D_*D_], g_wol[D_*D_];

// ---------------- PTX helpers (arch-generic sm_80-era only) -----------------
__device__ __forceinline__ uint32_t s2u(const void* p) {
    uint32_t a;
    asm("{ .reg .u64 t; cvta.to.shared.u64 t, %1; cvt.u32.u64 %0, t; }" : "=r"(a) : "l"(p));
    return a;
}
#define CPA16(d, s) asm volatile("cp.async.cg.shared.global [%0], [%1], 16;" :: "r"(d), "l"(s))
#define CPC()       asm volatile("cp.async.commit_group;" ::: "memory")
#define CPW(n)      asm volatile("cp.async.wait_group %0;" :: "n"(n) : "memory")

__device__ __forceinline__ void ldm_x4(uint32_t* r, uint32_t addr) {
    asm volatile("ldmatrix.sync.aligned.m8n8.x4.shared.b16 {%0,%1,%2,%3}, [%4];"
                 : "=r"(r[0]), "=r"(r[1]), "=r"(r[2]), "=r"(r[3]) : "r"(addr));
}
__device__ __forceinline__ void ldm_x4_t(uint32_t* r, uint32_t addr) {
    asm volatile("ldmatrix.sync.aligned.m8n8.x4.trans.shared.b16 {%0,%1,%2,%3}, [%4];"
                 : "=r"(r[0]), "=r"(r[1]), "=r"(r[2]), "=r"(r[3]) : "r"(addr));
}
__device__ __forceinline__ void mma_f16(float* d, const uint32_t* a, const uint32_t* b) {
    asm volatile("mma.sync.aligned.m16n8k16.row.col.f32.f16.f16.f32 "
                 "{%0,%1,%2,%3}, {%4,%5,%6,%7}, {%8,%9}, {%0,%1,%2,%3};"
                 : "+f"(d[0]), "+f"(d[1]), "+f"(d[2]), "+f"(d[3])
                 : "r"(a[0]), "r"(a[1]), "r"(a[2]), "r"(a[3]), "r"(b[0]), "r"(b[1]));
}
__device__ __forceinline__ void split2h(float v0, float v1, uint32_t& hi, uint32_t& lo) {
    __half2 hb = __float22half2_rn(make_float2(v0, v1));
    float2 hfv = __half22float2(hb);
    __half2 lb = __float22half2_rn(make_float2(v0 - hfv.x, v1 - hfv.y));
    hi = *(uint32_t*)&hb;
    lo = *(uint32_t*)&lb;
}
__device__ __forceinline__ uint32_t pack2h(float v0, float v1) {
    __half2 p = __float22half2_rn(make_float2(v0, v1));
    return *(uint32_t*)&p;
}

// ---------------- fp32 -> (hi,lo) fp16 split --------------------------------
__global__ void cvt_split(const float* __restrict__ x, hf16* __restrict__ h,
                          hf16* __restrict__ l, int n4)
{
    int i = blockIdx.x * blockDim.x + threadIdx.x;
    if (i >= n4) return;
    float4 v = ((const float4*)x)[i];
    float vs[4] = {v.x, v.y, v.z, v.w};
    #pragma unroll
    for (int j = 0; j < 4; j++) {
        hf16 hb = __float2half_rn(vs[j]);
        h[i*4+j] = hb;
        l[i*4+j] = __float2half_rn(vs[j] - __half2float(hb));
    }
}

// ---------------- batched W[K,N] -> Wt[N,K] hi/lo split (z picks matrix) ----
__global__ void transpose_split4(const float* __restrict__ W0, const float* __restrict__ W1,
                                 const float* __restrict__ W2, const float* __restrict__ W3)
{
    __shared__ float t[32][33];
    int z = blockIdx.z;
    const float* W = z == 0 ? W0 : z == 1 ? W1 : z == 2 ? W2 : W3;
    hf16* Th = z == 0 ? g_wqh : z == 1 ? g_wkh : z == 2 ? g_wvh : g_woh;
    hf16* Tl = z == 0 ? g_wql : z == 1 ? g_wkl : z == 2 ? g_wvl : g_wol;

    int bx = blockIdx.x * 32, by = blockIdx.y * 32;
    int tx = threadIdx.x, ty = threadIdx.y;
    #pragma unroll
    for (int i = 0; i < 4; i++)
        t[ty + i*8][tx] = W[(size_t)(by + ty + i*8) * D_ + bx + tx];
    __syncthreads();
    #pragma unroll
    for (int i = 0; i < 4; i++) {
        float vv = t[tx][ty + i*8];
        hf16 hb = __float2half_rn(vv);
        size_t o = (size_t)(bx + ty + i*8) * D_ + by + tx;
        Th[o] = hb;
        Tl[o] = __float2half_rn(vv - __half2float(hb));
    }
}

// ---------------- shared GEMM body: C = A @ B^T (+bias), split-fp16 ---------
// p3 (runtime): include the 3rd (Al*Bh) pass; when false, A_lo tile is not
// even loaded. Single instantiation per OUT_F32 to keep code size in I$.
#define NCHUNK 16
#define STAGE_BYTES 65536
template<bool OUT_F32>
__device__ __forceinline__ void gemm_body(
    const hf16* __restrict__ Ah, const hf16* __restrict__ Al,
    const hf16* __restrict__ Bh, const hf16* __restrict__ Bl,
    const float* __restrict__ bias, float* __restrict__ Cf,
    hf16* __restrict__ Ch, hf16* __restrict__ Cl, char* smem, bool p3)
{
    uint32_t sb = s2u(smem);
    int tid = threadIdx.x, wid = tid >> 5, lane = tid & 31;
    int wr = wid >> 2, wc = wid & 3;
    int rowBase = blockIdx.y * 128, colBase = blockIdx.x * 128;

    const hf16* bases[4] = {
        Ah + (size_t)rowBase * D_, Al + (size_t)rowBase * D_,
        Bh + (size_t)colBase * D_, Bl + (size_t)colBase * D_ };

    #define LOAD_CHUNK(c_, st_) do { \
        int k0_ = (c_) * 64; \
        uint32_t d0_ = sb + (st_) * STAGE_BYTES; \
        _Pragma("unroll") \
        for (int t_ = 0; t_ < 4; t_++) { \
            if (t_ == 1 && !p3) continue; \
            const hf16* s_ = bases[t_]; \
            _Pragma("unroll") \
            for (int i_ = 0; i_ < 4; i_++) { \
                int idx_ = tid + i_ * 256; \
                int rr_ = idx_ >> 3, gq_ = idx_ & 7; \
                uint32_t dd_ = d0_ + t_ * 16384 + rr_ * 128 + ((gq_ ^ (rr_ & 7)) << 4); \
                CPA16(dd_, s_ + (size_t)rr_ * D_ + k0_ + gq_ * 8); \
            } \
        } \
        CPC(); \
    } while (0)

    LOAD_CHUNK(0, 0);
    LOAD_CHUNK(1, 1);

    float acc[4][4][4] = {};

    for (int c = 0; c < NCHUNK; c++) {
        if (c < NCHUNK - 1) CPW(1); else CPW(0);
        __syncthreads();
        if (c + 2 < NCHUNK) LOAD_CHUNK(c + 2, (c + 2) % 3);

        uint32_t stg = sb + (c % 3) * STAGE_BYTES;

        #pragma unroll
        for (int ks = 0; ks < 4; ks++) {
            uint32_t a_hi[4][4], a_lo[4][4];
            #pragma unroll
            for (int mi = 0; mi < 4; mi++) {
                int row = wr * 64 + mi * 16 + (lane & 15);
                int kg  = ks * 2 + (lane >> 4);
                uint32_t addr = stg + row * 128 + ((kg ^ (row & 7)) << 4);
                ldm_x4(a_hi[mi], addr);
                if (p3) ldm_x4(a_lo[mi], addr + 16384);
            }
            uint32_t b_hi[2][4], b_lo[2][4];
            #pragma unroll
            for (int nj = 0; nj < 2; nj++) {
                int rowb = wc * 32 + nj * 16 + (lane & 7) + ((lane & 16) ? 8 : 0);
                int kg   = ks * 2 + ((lane >> 3) & 1);
                uint32_t addr = stg + 32768 + rowb * 128 + ((kg ^ (rowb & 7)) << 4);
                ldm_x4(b_hi[nj], addr);
                ldm_x4(b_lo[nj], addr + 16384);
            }
            #pragma unroll
            for (int mi = 0; mi < 4; mi++)
                #pragma unroll
                for (int ni = 0; ni < 4; ni++) {
                    const uint32_t* bh = &b_hi[ni >> 1][(ni & 1) * 2];
                    const uint32_t* bl = &b_lo[ni >> 1][(ni & 1) * 2];
                    mma_f16(acc[mi][ni], a_hi[mi], bh);
                    mma_f16(acc[mi][ni], a_hi[mi], bl);
                    if (p3) mma_f16(acc[mi][ni], a_lo[mi], bh);
                }
        }
    }

    #pragma unroll
    for (int ni = 0; ni < 4; ni++) {
        int col = colBase + wc * 32 + ni * 8 + (lane & 3) * 2;
        float2 bb = bias ? *(const float2*)&bias[col] : make_float2(0.f, 0.f);
        #pragma unroll
        for (int mi = 0; mi < 4; mi++) {
            int row = rowBase + wr * 64 + mi * 16 + (lane >> 2);
            float v00 = acc[mi][ni][0] + bb.x, v01 = acc[mi][ni][1] + bb.y;
            float v10 = acc[mi][ni][2] + bb.x, v11 = acc[mi][ni][3] + bb.y;
            if (OUT_F32) {
                *(float2*)&Cf[(size_t)row * D_ + col]       = make_float2(v00, v01);
                *(float2*)&Cf[(size_t)(row + 8) * D_ + col] = make_float2(v10, v11);
            } else if (Cl) {
                uint32_t h0, l0, h1, l1;
                split2h(v00, v01, h0, l0);
                split2h(v10, v11, h1, l1);
                *(uint32_t*)&Ch[(size_t)row * D_ + col]       = h0;
                *(uint32_t*)&Cl[(size_t)row * D_ + col]       = l0;
                *(uint32_t*)&Ch[(size_t)(row + 8) * D_ + col] = h1;
                *(uint32_t*)&Cl[(size_t)(row + 8) * D_ + col] = l1;
            } else {
                *(uint32_t*)&Ch[(size_t)row * D_ + col]       = pack2h(v00, v01);
                *(uint32_t*)&Ch[(size_t)(row + 8) * D_ + col] = pack2h(v10, v11);
            }
        }
    }
}

// fused Q/K/V projection: blockIdx.z selects weight/bias/output.
// Q: 2-pass hi-only (flash uses qh only). K: 3-pass hi+lo (lo feeds QK^T).
// V: 2-pass hi-only.
__global__ void __launch_bounds__(256, 1)
gemm_qkv(const float* __restrict__ bq, const float* __restrict__ bv)
{
    extern __shared__ char smem[];
    int z = blockIdx.z;
    const hf16* Bh = z == 0 ? g_wqh : z == 1 ? g_wkh : g_wvh;
    const hf16* Bl = z == 0 ? g_wql : z == 1 ? g_wkl : g_wvl;
    const float* bias = z == 0 ? bq : z == 1 ? (const float*)nullptr : bv;
    hf16* Ch = z == 0 ? g_qh : z == 1 ? g_kh : g_vh;
    hf16* Cl = z == 1 ? g_kl : (hf16*)nullptr;
    gemm_body<false>(g_xh, g_xl, Bh, Bl, bias, nullptr, Ch, Cl, smem, z == 1);
}

// output projection: fp32 out, 2-pass (attn output already fp16-rounded)
__global__ void __launch_bounds__(256, 1)
gemm_o(const float* __restrict__ bo, float* __restrict__ out)
{
    extern __shared__ char smem[];
    gemm_body<true>(g_ah, g_ah, g_woh, g_wol, bo, out, nullptr, nullptr, smem, false);
}

// ---------------------------------------------------------------------------
// Tensor-core flash attention, fp16. CTA = 128 q-rows x one (b,h), 256
// threads = 8 warps x m16n64 (per-warp code identical to the proven R9/R13
// structure). 64-key chunks shared by all 8 warps; stage = KH|KL|VH (24KB);
// ~90KB smem -> 2 CTAs/SM = 16 warps/SM (vs 8 before).
// ---------------------------------------------------------------------------
#define FA_STG  16384              // Q hi: 128 rows x 128B
#define FA_STAGE_SZ 24576          // KH 8KB | KL 8KB | VH 8KB
#define FA_TB   (FA_STG + 3*FA_STAGE_SZ)
#define FA_SMEM (FA_TB + 2*192*4)
#define NKT     (S_/64)

__global__ void __launch_bounds__(256, 2)
flash_mma(const hf16* __restrict__ qh,
          const hf16* __restrict__ kh, const hf16* __restrict__ kl,
          const hf16* __restrict__ vh,
          const float* __restrict__ pb,
          hf16* __restrict__ oh)
{
    extern __shared__ char smem[];
    uint32_t sbase = s2u(smem);
    float* tb = (float*)(smem + FA_TB);

    int tid = threadIdx.x, w = tid >> 5, lane = tid & 31;
    int bh = blockIdx.y, b = bh >> 4, h = bh & 15;
    int q0 = blockIdx.x * 128;

    const float LOG2E = 1.4426950408889634f;
    const float c1L = 0.4785533905932738f * LOG2E;
    const float c2L = 0.3535533905932738f * LOG2E;

    size_t toff = (size_t)(b * S_) * D_ + h * HD_;
    const hf16* kvp[3] = {kh + toff, kl + toff, vh + toff};
    const hf16* qp = qh + toff;

    // ---- Q tile (128 rows x 64d, hi only), 16 KB ----
    #pragma unroll
    for (int i = 0; i < 4; i++) {
        int idx = tid + i * 256;           // 1024 granules
        int r = idx >> 3, g = idx & 7;
        uint32_t dd = sbase + r * 128 + ((g ^ (r & 7)) << 4);
        CPA16(dd, qp + (size_t)(q0 + r) * D_ + g * 8);
    }
    // 64-key chunk: KH | KL | VH at 8KB each (512 granules/tile, 2 iters)
    #define LOAD_KV(c_, st_) do { \
        int kt_ = (c_) * 64; \
        uint32_t d0_ = sbase + FA_STG + (st_) * FA_STAGE_SZ; \
        _Pragma("unroll") \
        for (int t_ = 0; t_ < 3; t_++) { \
            _Pragma("unroll") \
            for (int i_ = 0; i_ < 2; i_++) { \
                int idx_ = tid + i_ * 256; \
                int r_ = idx_ >> 3, g_ = idx_ & 7; \
                uint32_t dd_ = d0_ + t_ * 8192 + r_ * 128 + ((g_ ^ (r_ & 7)) << 4); \
                CPA16(dd_, kvp[t_] + (size_t)(kt_ + r_) * D_ + g_ * 8); \
            } \
        } \
        CPC(); \
    } while (0)

    // bias table: i-j in [-63, 127] -> 191 entries; 256 threads cover it
    #define FILL_TB(c_, buf_) do { \
        if (tid < 191) { \
            int rel_ = q0 - (c_) * 64 + (tid - 63); \
            rel_ = min(max(rel_, -(MAXD - 1)), MAXD - 1) + (MAXD - 1); \
            tb[(buf_) * 192 + tid] = c2L * __ldg(&pb[rel_ * H_ + h]); \
        } \
    } while (0)

    LOAD_KV(0, 0);
    LOAD_KV(1, 1);
    FILL_TB(0, 0);

    uint32_t qa_h[4][4];
    float o[8][4] = {};
    float m0 = -1e30f, m1 = -1e30f, l0 = 0.f, l1 = 0.f;

    for (int c = 0; c < NKT; c++) {
        if (c < NKT - 1) CPW(1); else CPW(0);
        __syncthreads();

        if (c == 0) {
            #pragma unroll
            for (int ks = 0; ks < 4; ks++) {
                int row = w * 16 + (lane & 15);
                int kg  = ks * 2 + (lane >> 4);
                uint32_t addr = sbase + row * 128 + ((kg ^ (row & 7)) << 4);
                ldm_x4(qa_h[ks], addr);
            }
        }
        if (c + 2 < NKT) LOAD_KV(c + 2, (c + 2) % 3);
        if (c + 1 < NKT) FILL_TB(c + 1, (c + 1) & 1);

        uint32_t stg = sbase + FA_STG + (c % 3) * FA_STAGE_SZ;
        const float* tbc = tb + (c & 1) * 192;

        // ---- S = Qh (Kh + Kl)  (2-pass split-fp16) ----
        float s[8][4] = {};
        #pragma unroll
        for (int ks = 0; ks < 4; ks++) {
            uint32_t bK_h[4][4], bK_l[4][4];
            #pragma unroll
            for (int nj = 0; nj < 4; nj++) {
                int rowb = nj * 16 + (lane & 7) + ((lane & 16) ? 8 : 0);
                int kg   = ks * 2 + ((lane >> 3) & 1);
                uint32_t addr = stg + rowb * 128 + ((kg ^ (rowb & 7)) << 4);
                ldm_x4(bK_h[nj], addr);
                ldm_x4(bK_l[nj], addr + 8192);
            }
            #pragma unroll
            for (int ni = 0; ni < 8; ni++) {
                const uint32_t* bh2 = &bK_h[ni >> 1][(ni & 1) * 2];
                const uint32_t* bl2 = &bK_l[ni >> 1][(ni & 1) * 2];
                mma_f16(s[ni], qa_h[ks], bh2);
                mma_f16(s[ni], qa_h[ks], bl2);
            }
        }

        // ---- bias + online softmax (exp2 domain) ----
        int i0 = w * 16 + (lane >> 2);
        int jb = 2 * (lane & 3);
        float t0 = -1e30f, t1 = -1e30f;
        #pragma unroll
        for (int ni = 0; ni < 8; ni++) {
            int tix = i0 - (8 * ni + jb) + 63;
            s[ni][0] = fmaf(c1L, s[ni][0], tbc[tix]);
            s[ni][1] = fmaf(c1L, s[ni][1], tbc[tix - 1]);
            s[ni][2] = fmaf(c1L, s[ni][2], tbc[tix + 8]);
            s[ni][3] = fmaf(c1L, s[ni][3], tbc[tix + 7]);
            t0 = fmaxf(t0, fmaxf(s[ni][0], s[ni][1]));
            t1 = fmaxf(t1, fmaxf(s[ni][2], s[ni][3]));
        }
        t0 = fmaxf(t0, __shfl_xor_sync(0xffffffffu, t0, 1));
        t0 = fmaxf(t0, __shfl_xor_sync(0xffffffffu, t0, 2));
        t1 = fmaxf(t1, __shfl_xor_sync(0xffffffffu, t1, 1));
        t1 = fmaxf(t1, __shfl_xor_sync(0xffffffffu, t1, 2));
        float m0n = fmaxf(m0, t0), m1n = fmaxf(m1, t1);
        float cr0 = exp2f(m0 - m0n), cr1 = exp2f(m1 - m1n);
        m0 = m0n; m1 = m1n;

        float ls0 = 0.f, ls1 = 0.f;
        #pragma unroll
        for (int ni = 0; ni < 8; ni++) {
            s[ni][0] = exp2f(s[ni][0] - m0);
            s[ni][1] = exp2f(s[ni][1] - m0);
            s[ni][2] = exp2f(s[ni][2] - m1);
            s[ni][3] = exp2f(s[ni][3] - m1);
            ls0 += s[ni][0] + s[ni][1];
            ls1 += s[ni][2] + s[ni][3];
        }
        l0 = l0 * cr0 + ls0;
        l1 = l1 * cr1 + ls1;
        if (cr0 != 1.f || cr1 != 1.f) {
            #pragma unroll
            for (int ni = 0; ni < 8; ni++) {
                o[ni][0] *= cr0; o[ni][1] *= cr0;
                o[ni][2] *= cr1; o[ni][3] *= cr1;
            }
        }

        // ---- O += P V (single-pass fp16) ----
        #pragma unroll
        for (int t = 0; t < 4; t++) {
            uint32_t a_h[4];
            a_h[0] = pack2h(s[2*t][0],   s[2*t][1]);
            a_h[1] = pack2h(s[2*t][2],   s[2*t][3]);
            a_h[2] = pack2h(s[2*t+1][0], s[2*t+1][1]);
            a_h[3] = pack2h(s[2*t+1][2], s[2*t+1][3]);

            uint32_t bV_h[4][4];
            #pragma unroll
            for (int vj = 0; vj < 4; vj++) {
                int rowv = t * 16 + (lane & 7) + ((lane & 8) ? 8 : 0);
                int gq   = 2 * vj + ((lane >> 4) & 1);
                uint32_t addr = stg + 16384 + rowv * 128 + ((gq ^ (rowv & 7)) << 4);
                ldm_x4_t(bV_h[vj], addr);
            }
            #pragma unroll
            for (int ni = 0; ni < 8; ni++) {
                const uint32_t* bh2 = &bV_h[ni >> 1][(ni & 1) * 2];
                mma_f16(o[ni], a_h, bh2);
            }
        }
    }

    l0 += __shfl_xor_sync(0xffffffffu, l0, 1);
    l0 += __shfl_xor_sync(0xffffffffu, l0, 2);
    l1 += __shfl_xor_sync(0xffffffffu, l1, 1);
    l1 += __shfl_xor_sync(0xffffffffu, l1, 2);
    float inv0 = 1.f / l0, inv1 = 1.f / l1;

    int row0 = b * S_ + q0 + w * 16 + (lane >> 2);
    #pragma unroll
    for (int ni = 0; ni < 8; ni++) {
        int col = h * HD_ + 8 * ni + 2 * (lane & 3);
        *(uint32_t*)&oh[(size_t)row0 * D_ + col]       = pack2h(o[ni][0] * inv0, o[ni][1] * inv0);
        *(uint32_t*)&oh[(size_t)(row0 + 8) * D_ + col] = pack2h(o[ni][2] * inv1, o[ni][3] * inv1);
    }
}

// ---------------------------------------------------------------------------
extern "C" void kernel_launch(void* const* d_in, const int* in_sizes, int n_in,
                              void* d_out, int out_size)
{
    const float* x  = (const float*)d_in[0];
    const float* Wq = (const float*)d_in[1];
    const float* bq = (const float*)d_in[2];
    const float* Wk = (const float*)d_in[3];
    const float* Wv = (const float*)d_in[4];
    const float* bv = (const float*)d_in[5];
    const float* Wo = (const float*)d_in[6];
    const float* bo = (const float*)d_in[7];
    const float* pb = (const float*)d_in[8];
    float* out = (float*)d_out;

    hf16 *xh, *xl, *qh, *kh, *kl, *vh, *ah;
    cudaGetSymbolAddress((void**)&xh, g_xh); cudaGetSymbolAddress((void**)&xl, g_xl);
    cudaGetSymbolAddress((void**)&qh, g_qh);
    cudaGetSymbolAddress((void**)&kh, g_kh); cudaGetSymbolAddress((void**)&kl, g_kl);
    cudaGetSymbolAddress((void**)&vh, g_vh);
    cudaGetSymbolAddress((void**)&ah, g_ah);

    const int M = B_ * S_;
    const int NELEM4 = M * D_ / 4;

    cvt_split<<<NELEM4 / 256, 256>>>(x, xh, xl, NELEM4);
    dim3 tGrid(D_ / 32, D_ / 32, 4), tBlk(32, 8);
    transpose_split4<<<tGrid, tBlk>>>(Wq, Wk, Wv, Wo);

    int gsmem = 3 * STAGE_BYTES;
    cudaFuncSetAttribute(gemm_qkv, cudaFuncAttributeMaxDynamicSharedMemorySize, gsmem);
    cudaFuncSetAttribute(gemm_o,   cudaFuncAttributeMaxDynamicSharedMemorySize, gsmem);

    dim3 qkvGrid(D_ / 128, M / 128, 3);          // (8, 32, 3)
    gemm_qkv<<<qkvGrid, 256, gsmem>>>(bq, bv);

    cudaFuncSetAttribute(flash_mma, cudaFuncAttributeMaxDynamicSharedMemorySize, FA_SMEM);
    dim3 fGrid(S_ / 128, B_ * H_);               // (16, 32)
    flash_mma<<<fGrid, 256, FA_SMEM>>>(qh, kh, kl, vh, pb, ah);

    dim3 oGrid(D_ / 128, M / 128);               // (8, 32)
    gemm_o<<<oGrid, 256, gsmem>>>(bo, out);
}

// round 15
// speedup vs baseline: 1.7810x; 1.2504x over previous
#include <cuda_runtime.h>
#include <cuda_fp16.h>
#include <cstdint>

#define B_ 2
#define S_ 2048
#define D_ 1024
#define H_ 16
#define HD_ 64
#define MAXD 1024

typedef __half hf16;

// ---------------- scratch (__device__ globals; no allocs allowed) -----------
__device__ hf16 g_xh[B_*S_*D_], g_xl[B_*S_*D_];
__device__ hf16 g_qh[B_*S_*D_];
__device__ hf16 g_kh[B_*S_*D_];
__device__ hf16 g_vh[B_*S_*D_];
__device__ hf16 g_ah[B_*S_*D_];
__device__ hf16 g_wqh[D_*D_], g_wql[D_*D_];
__device__ hf16 g_wkh[D_*D_], g_wkl[D_*D_];
__device__ hf16 g_wvh[D_*D_], g_wvl[D_*D_];
__device__ hf16 g_woh[D_*D_], g_wol[D_*D_];

// ---------------- PTX helpers (arch-generic sm_80-era only) -----------------
__device__ __forceinline__ uint32_t s2u(const void* p) {
    uint32_t a;
    asm("{ .reg .u64 t; cvta.to.shared.u64 t, %1; cvt.u32.u64 %0, t; }" : "=r"(a) : "l"(p));
    return a;
}
#define CPA16(d, s) asm volatile("cp.async.cg.shared.global [%0], [%1], 16;" :: "r"(d), "l"(s))
#define CPC()       asm volatile("cp.async.commit_group;" ::: "memory")
#define CPW(n)      asm volatile("cp.async.wait_group %0;" :: "n"(n) : "memory")

__device__ __forceinline__ void ldm_x4(uint32_t* r, uint32_t addr) {
    asm volatile("ldmatrix.sync.aligned.m8n8.x4.shared.b16 {%0,%1,%2,%3}, [%4];"
                 : "=r"(r[0]), "=r"(r[1]), "=r"(r[2]), "=r"(r[3]) : "r"(addr));
}
__device__ __forceinline__ void ldm_x4_t(uint32_t* r, uint32_t addr) {
    asm volatile("ldmatrix.sync.aligned.m8n8.x4.trans.shared.b16 {%0,%1,%2,%3}, [%4];"
                 : "=r"(r[0]), "=r"(r[1]), "=r"(r[2]), "=r"(r[3]) : "r"(addr));
}
__device__ __forceinline__ void mma_f16(float* d, const uint32_t* a, const uint32_t* b) {
    asm volatile("mma.sync.aligned.m16n8k16.row.col.f32.f16.f16.f32 "
                 "{%0,%1,%2,%3}, {%4,%5,%6,%7}, {%8,%9}, {%0,%1,%2,%3};"
                 : "+f"(d[0]), "+f"(d[1]), "+f"(d[2]), "+f"(d[3])
                 : "r"(a[0]), "r"(a[1]), "r"(a[2]), "r"(a[3]), "r"(b[0]), "r"(b[1]));
}
__device__ __forceinline__ void split2h(float v0, float v1, uint32_t& hi, uint32_t& lo) {
    __half2 hb = __float22half2_rn(make_float2(v0, v1));
    float2 hfv = __half22float2(hb);
    __half2 lb = __float22half2_rn(make_float2(v0 - hfv.x, v1 - hfv.y));
    hi = *(uint32_t*)&hb;
    lo = *(uint32_t*)&lb;
}
__device__ __forceinline__ uint32_t pack2h(float v0, float v1) {
    __half2 p = __float22half2_rn(make_float2(v0, v1));
    return *(uint32_t*)&p;
}

// ---------------- fp32 -> (hi,lo) fp16 split --------------------------------
__global__ void cvt_split(const float* __restrict__ x, hf16* __restrict__ h,
                          hf16* __restrict__ l, int n4)
{
    int i = blockIdx.x * blockDim.x + threadIdx.x;
    if (i >= n4) return;
    float4 v = ((const float4*)x)[i];
    float vs[4] = {v.x, v.y, v.z, v.w};
    #pragma unroll
    for (int j = 0; j < 4; j++) {
        hf16 hb = __float2half_rn(vs[j]);
        h[i*4+j] = hb;
        l[i*4+j] = __float2half_rn(vs[j] - __half2float(hb));
    }
}

// ---------------- batched W[K,N] -> Wt[N,K] hi/lo split (z picks matrix) ----
__global__ void transpose_split4(const float* __restrict__ W0, const float* __restrict__ W1,
                                 const float* __restrict__ W2, const float* __restrict__ W3)
{
    __shared__ float t[32][33];
    int z = blockIdx.z;
    const float* W = z == 0 ? W0 : z == 1 ? W1 : z == 2 ? W2 : W3;
    hf16* Th = z == 0 ? g_wqh : z == 1 ? g_wkh : z == 2 ? g_wvh : g_woh;
    hf16* Tl = z == 0 ? g_wql : z == 1 ? g_wkl : z == 2 ? g_wvl : g_wol;

    int bx = blockIdx.x * 32, by = blockIdx.y * 32;
    int tx = threadIdx.x, ty = threadIdx.y;
    #pragma unroll
    for (int i = 0; i < 4; i++)
        t[ty + i*8][tx] = W[(size_t)(by + ty + i*8) * D_ + bx + tx];
    __syncthreads();
    #pragma unroll
    for (int i = 0; i < 4; i++) {
        float vv = t[tx][ty + i*8];
        hf16 hb = __float2half_rn(vv);
        size_t o = (size_t)(bx + ty + i*8) * D_ + by + tx;
        Th[o] = hb;
        Tl[o] = __float2half_rn(vv - __half2float(hb));
    }
}

// ---------------- shared GEMM body: C = A @ B^T (+bias), split-fp16 ---------
// p3 (runtime): include the 3rd (Al*Bh) pass; when false, A_lo tile is not
// even loaded. Single instantiation per OUT_F32 to keep code size in I$.
#define NCHUNK 16
#define STAGE_BYTES 65536
template<bool OUT_F32>
__device__ __forceinline__ void gemm_body(
    const hf16* __restrict__ Ah, const hf16* __restrict__ Al,
    const hf16* __restrict__ Bh, const hf16* __restrict__ Bl,
    const float* __restrict__ bias, float* __restrict__ Cf,
    hf16* __restrict__ Ch, hf16* __restrict__ Cl, char* smem, bool p3)
{
    uint32_t sb = s2u(smem);
    int tid = threadIdx.x, wid = tid >> 5, lane = tid & 31;
    int wr = wid >> 2, wc = wid & 3;
    int rowBase = blockIdx.y * 128, colBase = blockIdx.x * 128;

    const hf16* bases[4] = {
        Ah + (size_t)rowBase * D_, Al + (size_t)rowBase * D_,
        Bh + (size_t)colBase * D_, Bl + (size_t)colBase * D_ };

    #define LOAD_CHUNK(c_, st_) do { \
        int k0_ = (c_) * 64; \
        uint32_t d0_ = sb + (st_) * STAGE_BYTES; \
        _Pragma("unroll") \
        for (int t_ = 0; t_ < 4; t_++) { \
            if (t_ == 1 && !p3) continue; \
            const hf16* s_ = bases[t_]; \
            _Pragma("unroll") \
            for (int i_ = 0; i_ < 4; i_++) { \
                int idx_ = tid + i_ * 256; \
                int rr_ = idx_ >> 3, gq_ = idx_ & 7; \
                uint32_t dd_ = d0_ + t_ * 16384 + rr_ * 128 + ((gq_ ^ (rr_ & 7)) << 4); \
                CPA16(dd_, s_ + (size_t)rr_ * D_ + k0_ + gq_ * 8); \
            } \
        } \
        CPC(); \
    } while (0)

    LOAD_CHUNK(0, 0);
    LOAD_CHUNK(1, 1);

    float acc[4][4][4] = {};

    for (int c = 0; c < NCHUNK; c++) {
        if (c < NCHUNK - 1) CPW(1); else CPW(0);
        __syncthreads();
        if (c + 2 < NCHUNK) LOAD_CHUNK(c + 2, (c + 2) % 3);

        uint32_t stg = sb + (c % 3) * STAGE_BYTES;

        #pragma unroll
        for (int ks = 0; ks < 4; ks++) {
            uint32_t a_hi[4][4], a_lo[4][4];
            #pragma unroll
            for (int mi = 0; mi < 4; mi++) {
                int row = wr * 64 + mi * 16 + (lane & 15);
                int kg  = ks * 2 + (lane >> 4);
                uint32_t addr = stg + row * 128 + ((kg ^ (row & 7)) << 4);
                ldm_x4(a_hi[mi], addr);
                if (p3) ldm_x4(a_lo[mi], addr + 16384);
            }
            uint32_t b_hi[2][4], b_lo[2][4];
            #pragma unroll
            for (int nj = 0; nj < 2; nj++) {
                int rowb = wc * 32 + nj * 16 + (lane & 7) + ((lane & 16) ? 8 : 0);
                int kg   = ks * 2 + ((lane >> 3) & 1);
                uint32_t addr = stg + 32768 + rowb * 128 + ((kg ^ (rowb & 7)) << 4);
                ldm_x4(b_hi[nj], addr);
                ldm_x4(b_lo[nj], addr + 16384);
            }
            #pragma unroll
            for (int mi = 0; mi < 4; mi++)
                #pragma unroll
                for (int ni = 0; ni < 4; ni++) {
                    const uint32_t* bh = &b_hi[ni >> 1][(ni & 1) * 2];
                    const uint32_t* bl = &b_lo[ni >> 1][(ni & 1) * 2];
                    mma_f16(acc[mi][ni], a_hi[mi], bh);
                    mma_f16(acc[mi][ni], a_hi[mi], bl);
                    if (p3) mma_f16(acc[mi][ni], a_lo[mi], bh);
                }
        }
    }

    #pragma unroll
    for (int ni = 0; ni < 4; ni++) {
        int col = colBase + wc * 32 + ni * 8 + (lane & 3) * 2;
        float2 bb = bias ? *(const float2*)&bias[col] : make_float2(0.f, 0.f);
        #pragma unroll
        for (int mi = 0; mi < 4; mi++) {
            int row = rowBase + wr * 64 + mi * 16 + (lane >> 2);
            float v00 = acc[mi][ni][0] + bb.x, v01 = acc[mi][ni][1] + bb.y;
            float v10 = acc[mi][ni][2] + bb.x, v11 = acc[mi][ni][3] + bb.y;
            if (OUT_F32) {
                *(float2*)&Cf[(size_t)row * D_ + col]       = make_float2(v00, v01);
                *(float2*)&Cf[(size_t)(row + 8) * D_ + col] = make_float2(v10, v11);
            } else if (Cl) {
                uint32_t h0, l0, h1, l1;
                split2h(v00, v01, h0, l0);
                split2h(v10, v11, h1, l1);
                *(uint32_t*)&Ch[(size_t)row * D_ + col]       = h0;
                *(uint32_t*)&Cl[(size_t)row * D_ + col]       = l0;
                *(uint32_t*)&Ch[(size_t)(row + 8) * D_ + col] = h1;
                *(uint32_t*)&Cl[(size_t)(row + 8) * D_ + col] = l1;
            } else {
                *(uint32_t*)&Ch[(size_t)row * D_ + col]       = pack2h(v00, v01);
                *(uint32_t*)&Ch[(size_t)(row + 8) * D_ + col] = pack2h(v10, v11);
            }
        }
    }
}

// fused Q/K/V projection: blockIdx.z selects weight/bias/output.
// All 2-pass hi-only now (flash consumes qh, kh, vh only).
__global__ void __launch_bounds__(256, 1)
gemm_qkv(const float* __restrict__ bq, const float* __restrict__ bv)
{
    extern __shared__ char smem[];
    int z = blockIdx.z;
    const hf16* Bh = z == 0 ? g_wqh : z == 1 ? g_wkh : g_wvh;
    const hf16* Bl = z == 0 ? g_wql : z == 1 ? g_wkl : g_wvl;
    const float* bias = z == 0 ? bq : z == 1 ? (const float*)nullptr : bv;
    hf16* Ch = z == 0 ? g_qh : z == 1 ? g_kh : g_vh;
    gemm_body<false>(g_xh, g_xl, Bh, Bl, bias, nullptr, Ch, nullptr, smem, false);
}

// output projection: fp32 out, 2-pass (attn output already fp16-rounded)
__global__ void __launch_bounds__(256, 1)
gemm_o(const float* __restrict__ bo, float* __restrict__ out)
{
    extern __shared__ char smem[];
    gemm_body<true>(g_ah, g_ah, g_woh, g_wol, bo, out, nullptr, nullptr, smem, false);
}

// ---------------------------------------------------------------------------
// Tensor-core flash attention, fp16. CTA = 128 q-rows x one (b,h), 256
// threads = 8 warps x m16n64. 64-key chunks; stage = KH|VH (16KB); ~66KB
// smem -> 2 CTAs/SM. S = Qh Kh (1-pass); O = P V (1-pass).
// ---------------------------------------------------------------------------
#define FA_STG  16384              // Q hi: 128 rows x 128B
#define FA_STAGE_SZ 16384          // KH 8KB | VH 8KB
#define FA_TB   (FA_STG + 3*FA_STAGE_SZ)
#define FA_SMEM (FA_TB + 2*192*4)
#define NKT     (S_/64)

__global__ void __launch_bounds__(256, 2)
flash_mma(const hf16* __restrict__ qh,
          const hf16* __restrict__ kh,
          const hf16* __restrict__ vh,
          const float* __restrict__ pb,
          hf16* __restrict__ oh)
{
    extern __shared__ char smem[];
    uint32_t sbase = s2u(smem);
    float* tb = (float*)(smem + FA_TB);

    int tid = threadIdx.x, w = tid >> 5, lane = tid & 31;
    int bh = blockIdx.y, b = bh >> 4, h = bh & 15;
    int q0 = blockIdx.x * 128;

    const float LOG2E = 1.4426950408889634f;
    const float c1L = 0.4785533905932738f * LOG2E;
    const float c2L = 0.3535533905932738f * LOG2E;

    size_t toff = (size_t)(b * S_) * D_ + h * HD_;
    const hf16* kvp[2] = {kh + toff, vh + toff};
    const hf16* qp = qh + toff;

    // ---- Q tile (128 rows x 64d, hi only), 16 KB ----
    #pragma unroll
    for (int i = 0; i < 4; i++) {
        int idx = tid + i * 256;           // 1024 granules
        int r = idx >> 3, g = idx & 7;
        uint32_t dd = sbase + r * 128 + ((g ^ (r & 7)) << 4);
        CPA16(dd, qp + (size_t)(q0 + r) * D_ + g * 8);
    }
    // 64-key chunk: KH | VH at 8KB each (512 granules/tile, 2 iters)
    #define LOAD_KV(c_, st_) do { \
        int kt_ = (c_) * 64; \
        uint32_t d0_ = sbase + FA_STG + (st_) * FA_STAGE_SZ; \
        _Pragma("unroll") \
        for (int t_ = 0; t_ < 2; t_++) { \
            _Pragma("unroll") \
            for (int i_ = 0; i_ < 2; i_++) { \
                int idx_ = tid + i_ * 256; \
                int r_ = idx_ >> 3, g_ = idx_ & 7; \
                uint32_t dd_ = d0_ + t_ * 8192 + r_ * 128 + ((g_ ^ (r_ & 7)) << 4); \
                CPA16(dd_, kvp[t_] + (size_t)(kt_ + r_) * D_ + g_ * 8); \
            } \
        } \
        CPC(); \
    } while (0)

    // bias table: i-j in [-63, 127] -> 191 entries; 256 threads cover it
    #define FILL_TB(c_, buf_) do { \
        if (tid < 191) { \
            int rel_ = q0 - (c_) * 64 + (tid - 63); \
            rel_ = min(max(rel_, -(MAXD - 1)), MAXD - 1) + (MAXD - 1); \
            tb[(buf_) * 192 + tid] = c2L * __ldg(&pb[rel_ * H_ + h]); \
        } \
    } while (0)

    LOAD_KV(0, 0);
    LOAD_KV(1, 1);
    FILL_TB(0, 0);

    uint32_t qa_h[4][4];
    float o[8][4] = {};
    float m0 = -1e30f, m1 = -1e30f, l0 = 0.f, l1 = 0.f;

    for (int c = 0; c < NKT; c++) {
        if (c < NKT - 1) CPW(1); else CPW(0);
        __syncthreads();

        if (c == 0) {
            #pragma unroll
            for (int ks = 0; ks < 4; ks++) {
                int row = w * 16 + (lane & 15);
                int kg  = ks * 2 + (lane >> 4);
                uint32_t addr = sbase + row * 128 + ((kg ^ (row & 7)) << 4);
                ldm_x4(qa_h[ks], addr);
            }
        }
        if (c + 2 < NKT) LOAD_KV(c + 2, (c + 2) % 3);
        if (c + 1 < NKT) FILL_TB(c + 1, (c + 1) & 1);

        uint32_t stg = sbase + FA_STG + (c % 3) * FA_STAGE_SZ;
        const float* tbc = tb + (c & 1) * 192;

        // ---- S = Qh Kh  (single-pass fp16) ----
        float s[8][4] = {};
        #pragma unroll
        for (int ks = 0; ks < 4; ks++) {
            uint32_t bK_h[4][4];
            #pragma unroll
            for (int nj = 0; nj < 4; nj++) {
                int rowb = nj * 16 + (lane & 7) + ((lane & 16) ? 8 : 0);
                int kg   = ks * 2 + ((lane >> 3) & 1);
                uint32_t addr = stg + rowb * 128 + ((kg ^ (rowb & 7)) << 4);
                ldm_x4(bK_h[nj], addr);
            }
            #pragma unroll
            for (int ni = 0; ni < 8; ni++) {
                const uint32_t* bh2 = &bK_h[ni >> 1][(ni & 1) * 2];
                mma_f16(s[ni], qa_h[ks], bh2);
            }
        }

        // ---- bias + online softmax (exp2 domain) ----
        int i0 = w * 16 + (lane >> 2);
        int jb = 2 * (lane & 3);
        float t0 = -1e30f, t1 = -1e30f;
        #pragma unroll
        for (int ni = 0; ni < 8; ni++) {
            int tix = i0 - (8 * ni + jb) + 63;
            s[ni][0] = fmaf(c1L, s[ni][0], tbc[tix]);
            s[ni][1] = fmaf(c1L, s[ni][1], tbc[tix - 1]);
            s[ni][2] = fmaf(c1L, s[ni][2], tbc[tix + 8]);
            s[ni][3] = fmaf(c1L, s[ni][3], tbc[tix + 7]);
            t0 = fmaxf(t0, fmaxf(s[ni][0], s[ni][1]));
            t1 = fmaxf(t1, fmaxf(s[ni][2], s[ni][3]));
        }
        t0 = fmaxf(t0, __shfl_xor_sync(0xffffffffu, t0, 1));
        t0 = fmaxf(t0, __shfl_xor_sync(0xffffffffu, t0, 2));
        t1 = fmaxf(t1, __shfl_xor_sync(0xffffffffu, t1, 1));
        t1 = fmaxf(t1, __shfl_xor_sync(0xffffffffu, t1, 2));
        float m0n = fmaxf(m0, t0), m1n = fmaxf(m1, t1);
        float cr0 = exp2f(m0 - m0n), cr1 = exp2f(m1 - m1n);
        m0 = m0n; m1 = m1n;

        float ls0 = 0.f, ls1 = 0.f;
        #pragma unroll
        for (int ni = 0; ni < 8; ni++) {
            s[ni][0] = exp2f(s[ni][0] - m0);
            s[ni][1] = exp2f(s[ni][1] - m0);
            s[ni][2] = exp2f(s[ni][2] - m1);
            s[ni][3] = exp2f(s[ni][3] - m1);
            ls0 += s[ni][0] + s[ni][1];
            ls1 += s[ni][2] + s[ni][3];
        }
        l0 = l0 * cr0 + ls0;
        l1 = l1 * cr1 + ls1;
        if (cr0 != 1.f || cr1 != 1.f) {
            #pragma unroll
            for (int ni = 0; ni < 8; ni++) {
                o[ni][0] *= cr0; o[ni][1] *= cr0;
                o[ni][2] *= cr1; o[ni][3] *= cr1;
            }
        }

        // ---- O += P V (single-pass fp16) ----
        #pragma unroll
        for (int t = 0; t < 4; t++) {
            uint32_t a_h[4];
            a_h[0] = pack2h(s[2*t][0],   s[2*t][1]);
            a_h[1] = pack2h(s[2*t][2],   s[2*t][3]);
            a_h[2] = pack2h(s[2*t+1][0], s[2*t+1][1]);
            a_h[3] = pack2h(s[2*t+1][2], s[2*t+1][3]);

            uint32_t bV_h[4][4];
            #pragma unroll
            for (int vj = 0; vj < 4; vj++) {
                int rowv = t * 16 + (lane & 7) + ((lane & 8) ? 8 : 0);
                int gq   = 2 * vj + ((lane >> 4) & 1);
                uint32_t addr = stg + 8192 + rowv * 128 + ((gq ^ (rowv & 7)) << 4);
                ldm_x4_t(bV_h[vj], addr);
            }
            #pragma unroll
            for (int ni = 0; ni < 8; ni++) {
                const uint32_t* bh2 = &bV_h[ni >> 1][(ni & 1) * 2];
                mma_f16(o[ni], a_h, bh2);
            }
        }
    }

    l0 += __shfl_xor_sync(0xffffffffu, l0, 1);
    l0 += __shfl_xor_sync(0xffffffffu, l0, 2);
    l1 += __shfl_xor_sync(0xffffffffu, l1, 1);
    l1 += __shfl_xor_sync(0xffffffffu, l1, 2);
    float inv0 = 1.f / l0, inv1 = 1.f / l1;

    int row0 = b * S_ + q0 + w * 16 + (lane >> 2);
    #pragma unroll
    for (int ni = 0; ni < 8; ni++) {
        int col = h * HD_ + 8 * ni + 2 * (lane & 3);
        *(uint32_t*)&oh[(size_t)row0 * D_ + col]       = pack2h(o[ni][0] * inv0, o[ni][1] * inv0);
        *(uint32_t*)&oh[(size_t)(row0 + 8) * D_ + col] = pack2h(o[ni][2] * inv1, o[ni][3] * inv1);
    }
}

// ---------------------------------------------------------------------------
extern "C" void kernel_launch(void* const* d_in, const int* in_sizes, int n_in,
                              void* d_out, int out_size)
{
    const float* x  = (const float*)d_in[0];
    const float* Wq = (const float*)d_in[1];
    const float* bq = (const float*)d_in[2];
    const float* Wk = (const float*)d_in[3];
    const float* Wv = (const float*)d_in[4];
    const float* bv = (const float*)d_in[5];
    const float* Wo = (const float*)d_in[6];
    const float* bo = (const float*)d_in[7];
    const float* pb = (const float*)d_in[8];
    float* out = (float*)d_out;

    hf16 *xh, *xl, *qh, *kh, *vh, *ah;
    cudaGetSymbolAddress((void**)&xh, g_xh); cudaGetSymbolAddress((void**)&xl, g_xl);
    cudaGetSymbolAddress((void**)&qh, g_qh);
    cudaGetSymbolAddress((void**)&kh, g_kh);
    cudaGetSymbolAddress((void**)&vh, g_vh);
    cudaGetSymbolAddress((void**)&ah, g_ah);

    const int M = B_ * S_;
    const int NELEM4 = M * D_ / 4;

    cvt_split<<<NELEM4 / 256, 256>>>(x, xh, xl, NELEM4);
    dim3 tGrid(D_ / 32, D_ / 32, 4), tBlk(32, 8);
    transpose_split4<<<tGrid, tBlk>>>(Wq, Wk, Wv, Wo);

    int gsmem = 3 * STAGE_BYTES;
    cudaFuncSetAttribute(gemm_qkv, cudaFuncAttributeMaxDynamicSharedMemorySize, gsmem);
    cudaFuncSetAttribute(gemm_o,   cudaFuncAttributeMaxDynamicSharedMemorySize, gsmem);

    dim3 qkvGrid(D_ / 128, M / 128, 3);          // (8, 32, 3)
    gemm_qkv<<<qkvGrid, 256, gsmem>>>(bq, bv);

    cudaFuncSetAttribute(flash_mma, cudaFuncAttributeMaxDynamicSharedMemorySize, FA_SMEM);
    dim3 fGrid(S_ / 128, B_ * H_);               // (16, 32)
    flash_mma<<<fGrid, 256, FA_SMEM>>>(qh, kh, vh, pb, ah);

    dim3 oGrid(D_ / 128, M / 128);               // (8, 32)
    gemm_o<<<oGrid, 256, gsmem>>>(bo, out);
}